// round 5
// baseline (speedup 1.0000x reference)
#include <cuda_runtime.h>

#define IC1 10
#define OC1 64
#define OC2 128
#define NB  64          // 2 images x 32 batch

__device__ int   g_cnt[NB][OC1][9];    // S, Rf, Rl, Cf, Cl, q_tl, q_tr, q_bl, q_br
__device__ float g_s2[NB][OC2];
__device__ float g_inv1[OC1],  g_beta1[OC1];
__device__ float g_inv2[OC2],  g_beta2[OC2];
__device__ float g_U[OC1][IC1][16];    // Winograd F(2x2,3x3) transformed weights

// packed fp32x2 (FFMA2) helpers
#define FMA_X2(d, a, b, c) \
    asm("fma.rn.f32x2 %0, %1, %2, %3;" : "=l"(d) : "l"(a), "l"(b), "l"(c))
#define PACK2(d, lo, hi) \
    asm("mov.b64 %0, {%1, %2};" : "=l"(d) : "r"(__float_as_uint(lo)), "r"(__float_as_uint(hi)))
#define UNPACK2(lo, hi, v) \
    asm("mov.b64 {%0, %1}, %2;" : "=r"(lo), "=r"(hi) : "l"(v))

// ---------------------------------------------------------------------------
// prep: zero counters, fold BN params, Winograd weight transform
// ---------------------------------------------------------------------------
__global__ void prep_kernel(const float* __restrict__ w1,
                            const float* __restrict__ g1, const float* __restrict__ b1,
                            const float* __restrict__ m1, const float* __restrict__ v1,
                            const float* __restrict__ g2, const float* __restrict__ b2,
                            const float* __restrict__ m2, const float* __restrict__ v2) {
    int gid = blockIdx.x * blockDim.x + threadIdx.x;
    int* c = &g_cnt[0][0][0];
    for (int i = gid; i < NB * OC1 * 9; i += gridDim.x * blockDim.x) c[i] = 0;
    if (blockIdx.x == 0) {
        int t = threadIdx.x;
        if (t < OC1) {
            float inv = g1[t] / sqrtf(v1[t] + 1e-5f);
            g_inv1[t] = inv;
            g_beta1[t] = b1[t] - m1[t] * inv;
        }
        if (t < OC2) {
            float inv = g2[t] / sqrtf(v2[t] + 1e-5f);
            g_inv2[t] = inv;
            g_beta2[t] = b2[t] - m2[t] * inv;
        }
    }
    if (gid < OC1 * IC1) {
        int oc = gid / IC1, ic = gid % IC1;
        const float* g = w1 + (oc * IC1 + ic) * 9;
        float gg[4][3];
#pragma unroll
        for (int cix = 0; cix < 3; ++cix) {
            float a = g[cix], b = g[3 + cix], d = g[6 + cix];
            gg[0][cix] = a;
            gg[1][cix] = 0.5f * (a + b + d);
            gg[2][cix] = 0.5f * (a - b + d);
            gg[3][cix] = d;
        }
        float* U = &g_U[oc][ic][0];
#pragma unroll
        for (int r = 0; r < 4; ++r) {
            float a = gg[r][0], b = gg[r][1], d = gg[r][2];
            U[r * 4 + 0] = a;
            U[r * 4 + 1] = 0.5f * (a + b + d);
            U[r * 4 + 2] = 0.5f * (a - b + d);
            U[r * 4 + 3] = d;
        }
    }
}

// ---------------------------------------------------------------------------
// stage A: Winograd conv1, j-split across lane pairs (l, l+16).
// grid (16, 16, 64), block 128. Warp = 16 tiles x 2 j-halves; block = 64 tiles
// (8x8 pooled region). V in registers (80 regs/thread), U broadcast from smem.
// ---------------------------------------------------------------------------
__global__ __launch_bounds__(128, 2) void stageA_kernel(const float* __restrict__ x0,
                                                        const float* __restrict__ x1) {
    __shared__ __align__(16) float sU[OC1 * IC1 * 16];  // 40960 B
    __shared__ float sBN[2 * OC1];                      //   512 B
    __shared__ __align__(8) float sin_[18 * 18];        //  1296 B
    __shared__ int sc[4][5][OC1];                       //  5120 B (total 47888)

    const int tid = threadIdx.x;
    const int warp = tid >> 5, lane = tid & 31;
    const int jh = lane >> 4;          // j-half: rows {0,1} or {2,3}
    const int lt = lane & 15;          // tile-lane
    const int tl = warp * 16 + lt;     // tile in block (0..63)
    const int ty = tl >> 3, tx = tl & 7;
    const int bx = blockIdx.x, by = blockIdx.y, n = blockIdx.z;
    const float* __restrict__ x = (n < 32) ? x0 : x1;
    const int b = n & 31;

    // load U (2560 float4), BN params, zero counters
    {
        const float4* gU4 = (const float4*)&g_U[0][0][0];
        float4* sU4 = (float4*)sU;
        for (int i = tid; i < 2560; i += 128) sU4[i] = __ldg(&gU4[i]);
    }
    if (tid < OC1) {
        sBN[tid] = __ldg(&g_inv1[tid]);
        sBN[OC1 + tid] = __ldg(&g_beta1[tid]);
    }
    for (int i = tid; i < 4 * 5 * OC1; i += 128) ((int*)sc)[i] = 0;

    const int gpy = by * 8 + ty, gpx = bx * 8 + tx;
    const bool edgeblk = (by == 0) | (by == 15) | (bx == 0) | (bx == 15);
    const int iy0 = by * 16 - 1;
    const int ix0 = bx * 16 - 1;
    const int rr = 2 * ty, cc = 2 * tx;

    // ---- phase 1: per-ic staging + half input transform -> V registers ----
    unsigned long long Vp[IC1][4];   // this half's 4 j-pairs per ic
#pragma unroll
    for (int ic = 0; ic < IC1; ++ic) {
        __syncthreads();
#pragma unroll
        for (int u = 0; u < 3; ++u) {
            int i = tid + u * 128;
            if (i < 324) {
                int rw = i / 18, cl = i % 18;
                int gy = iy0 + rw, gx = ix0 + cl;
                float v = 0.f;
                if ((unsigned)gy < 256u && (unsigned)gx < 256u)
                    v = __ldg(&x[((b * IC1 + ic) * 256 + gy) * 256 + gx]);
                sin_[i] = v;
            }
        }
        __syncthreads();

        // load 3 needed input rows (rows rr+jh .. rr+jh+2), 4 cols
        float e[3][4];
#pragma unroll
        for (int i = 0; i < 3; ++i) {
            const float2* p = (const float2*)&sin_[(rr + jh + i) * 18 + cc];
            float2 u0 = p[0], u1 = p[1];
            e[i][0] = u0.x; e[i][1] = u0.y; e[i][2] = u1.x; e[i][3] = u1.y;
        }
        // t rows for this half:
        // jh0 (rows 0,1): t_f = d0-d2, t_s = d1+d2   (e = d0,d1,d2)
        // jh1 (rows 2,3): t_f = d2-d1, t_s = d1-d3   (e = d1,d2,d3)
        float tf[4], ts[4];
        if (jh == 0) {
#pragma unroll
            for (int c2 = 0; c2 < 4; ++c2) { tf[c2] = e[0][c2] - e[2][c2]; ts[c2] = e[1][c2] + e[2][c2]; }
        } else {
#pragma unroll
            for (int c2 = 0; c2 < 4; ++c2) { tf[c2] = e[1][c2] - e[0][c2]; ts[c2] = e[0][c2] - e[2][c2]; }
        }
        // column transform per row
        PACK2(Vp[ic][0], tf[0] - tf[2], tf[1] + tf[2]);
        PACK2(Vp[ic][1], tf[2] - tf[1], tf[1] - tf[3]);
        PACK2(Vp[ic][2], ts[0] - ts[2], ts[1] + ts[2]);
        PACK2(Vp[ic][3], ts[2] - ts[1], ts[1] - ts[3]);
    }
    __syncthreads();

    // ---- phase 2: oc sweep, FFMA2 on this j-half, pair-exchange epilogue ----
#pragma unroll 1
    for (int oc = 0; oc < OC1; ++oc) {
        const float* ub = sU + oc * 160 + jh * 8;   // this half's 8 U floats per ic
        unsigned long long M0 = 0, M1 = 0, M2 = 0, M3 = 0;
#pragma unroll
        for (int ic = 0; ic < IC1; ++ic) {
            ulonglong2 ua = *(const ulonglong2*)(ub + ic * 16);       // pairs j0,j1
            ulonglong2 ubv = *(const ulonglong2*)(ub + ic * 16 + 4);  // pairs j2,j3
            FMA_X2(M0, ua.x,  Vp[ic][0], M0);
            FMA_X2(M1, ua.y,  Vp[ic][1], M1);
            FMA_X2(M2, ubv.x, Vp[ic][2], M2);
            FMA_X2(M3, ubv.y, Vp[ic][3], M3);
        }
        unsigned r0, r1, r2, r3, r4, r5, r6, r7;
        UNPACK2(r0, r1, M0); UNPACK2(r2, r3, M1);
        UNPACK2(r4, r5, M2); UNPACK2(r6, r7, M3);
        float m0 = __uint_as_float(r0), m1 = __uint_as_float(r1);
        float m2 = __uint_as_float(r2), m3 = __uint_as_float(r3);
        float m4 = __uint_as_float(r4), m5 = __uint_as_float(r5);
        float m6 = __uint_as_float(r6), m7 = __uint_as_float(r7);
        // row combines for this half's two rows
        float pax = m0 + m1 + m2, pay = m1 - m2 - m3;   // row 2*jh
        float pbx = m4 + m5 + m6, pby = m5 - m6 - m7;   // row 2*jh+1
        // exchange with partner half (lower receives rows 2,3)
        float oax = __shfl_xor_sync(0xffffffffu, pax, 16);
        float oay = __shfl_xor_sync(0xffffffffu, pay, 16);
        float obx = __shfl_xor_sync(0xffffffffu, pbx, 16);
        float oby = __shfl_xor_sync(0xffffffffu, pby, 16);
        // lower half: p0=pa, p1=pb, p2=oa, p3=ob
        float y00 = pax + pbx + oax;
        float y01 = pay + pby + oay;
        float y10 = pbx - oax - obx;
        float y11 = pby - oay - oby;

        float inv = sBN[oc], bet = sBN[OC1 + oc];
        float mx = fmaxf(fmaxf(y00, y01), fmaxf(y10, y11));
        float mn = fminf(fminf(y00, y01), fminf(y10, y11));
        float z = (inv >= 0.f ? mx : mn) * inv + bet;
        bool sp = (jh == 0) && (z > 1.0f);
        unsigned bal = __ballot_sync(0xffffffffu, sp);
        if (lane == 0 && bal) sc[warp][0][oc] = __popc(bal);
        if (edgeblk) {
            unsigned bR0 = __ballot_sync(0xffffffffu, sp && (gpy == 0));
            unsigned bR1 = __ballot_sync(0xffffffffu, sp && (gpy == 127));
            unsigned bC0 = __ballot_sync(0xffffffffu, sp && (gpx == 0));
            unsigned bC1 = __ballot_sync(0xffffffffu, sp && (gpx == 127));
            if (lane == 0) {
                if (bR0) sc[warp][1][oc] = __popc(bR0);
                if (bR1) sc[warp][2][oc] = __popc(bR1);
                if (bC0) sc[warp][3][oc] = __popc(bC0);
                if (bC1) sc[warp][4][oc] = __popc(bC1);
            }
            if (sp) {  // corner bits (unique writer per corner; pre-zeroed)
                if (gpy == 0   && gpx == 0)        g_cnt[n][oc][5] = 1;
                else if (gpy == 0   && gpx == 127) g_cnt[n][oc][6] = 1;
                else if (gpy == 127 && gpx == 0)   g_cnt[n][oc][7] = 1;
                else if (gpy == 127 && gpx == 127) g_cnt[n][oc][8] = 1;
            }
        }
    }
    __syncthreads();
    if (tid < OC1) {
#pragma unroll
        for (int j = 0; j < 5; ++j) {
            int v = sc[0][j][tid] + sc[1][j][tid] + sc[2][j][tid] + sc[3][j][tid];
            if (v) atomicAdd(&g_cnt[n][tid][j], v);
        }
    }
}

// ---------------------------------------------------------------------------
// stage B: analytic conv2-mean via T aggregates, BN2, spike -> g_s2
// ---------------------------------------------------------------------------
__global__ __launch_bounds__(256) void stageB_kernel(const float* __restrict__ w2) {
    __shared__ __align__(16) float sT[OC1 * 9];
    const int n = blockIdx.x, tid = threadIdx.x;
    const int lane = tid & 31, warp = tid >> 5;
    if (tid < OC1) {
        const int* c = g_cnt[n][tid];
        int S = c[0], Rf = c[1], Rl = c[2], Cf = c[3], Cl = c[4];
        int Re[3] = {Rl, 0, Rf};
        int Ce[3] = {Cl, 0, Cf};
        int Q[9]  = {c[8], 0, c[7],  0, 0, 0,  c[6], 0, c[5]};
#pragma unroll
        for (int k = 0; k < 9; ++k)
            sT[tid * 9 + k] = (float)(S - Re[k / 3] - Ce[k % 3] + Q[k]);
    }
    __syncthreads();
#pragma unroll 1
    for (int i = 0; i < 16; ++i) {
        const int o = warp * 16 + i;
        const float* wr = w2 + o * 576;
        float acc = 0.f;
#pragma unroll
        for (int t = 0; t < 18; ++t) {
            int j = t * 32 + lane;
            acc = fmaf(__ldg(&wr[j]), sT[j], acc);
        }
#pragma unroll
        for (int s = 16; s; s >>= 1) acc += __shfl_xor_sync(0xffffffffu, acc, s);
        if (lane == 0) {
            float z = acc * (1.f / 16384.f);
            z = z * g_inv2[o] + g_beta2[o];
            g_s2[n][o] = (z > 1.f) ? 1.f : 0.f;
        }
    }
}

// ---------------------------------------------------------------------------
// stage C: feat = |s0 - s1|, fc1+relu, fc2  -> out (32,5)
// ---------------------------------------------------------------------------
__global__ __launch_bounds__(256) void stageC_kernel(const float* __restrict__ fc1w,
                                                     const float* __restrict__ fc1b,
                                                     const float* __restrict__ fc2w,
                                                     const float* __restrict__ fc2b,
                                                     float* __restrict__ out) {
    __shared__ float f[128];
    __shared__ float h[64];
    const int n = blockIdx.x, tid = threadIdx.x;
    const int lane = tid & 31, warp = tid >> 5;
    if (tid < 128) f[tid] = fabsf(g_s2[n][tid] - g_s2[n + 32][tid]);
    __syncthreads();
#pragma unroll 1
    for (int i = 0; i < 8; ++i) {
        const int k = warp * 8 + i;
        const float* wr = fc1w + k * 128;
        float acc = 0.f;
#pragma unroll
        for (int t = 0; t < 4; ++t) {
            int j = t * 32 + lane;
            acc = fmaf(__ldg(&wr[j]), f[j], acc);
        }
#pragma unroll
        for (int s = 16; s; s >>= 1) acc += __shfl_xor_sync(0xffffffffu, acc, s);
        if (lane == 0) h[k] = fmaxf(acc + fc1b[k], 0.f);
    }
    __syncthreads();
    if (warp == 0) {
#pragma unroll 1
        for (int c = 0; c < 5; ++c) {
            const float* wr = fc2w + c * 64;
            float acc = fmaf(__ldg(&wr[lane]), h[lane], 0.f);
            acc = fmaf(__ldg(&wr[lane + 32]), h[lane + 32], acc);
#pragma unroll
            for (int s = 16; s; s >>= 1) acc += __shfl_xor_sync(0xffffffffu, acc, s);
            if (lane == 0) out[n * 5 + c] = acc + fc2b[c];
        }
    }
}

extern "C" void kernel_launch(void* const* d_in, const int* in_sizes, int n_in,
                              void* d_out, int out_size) {
    const float* x0   = (const float*)d_in[0];
    const float* x1   = (const float*)d_in[1];
    const float* w1   = (const float*)d_in[2];
    const float* b1g  = (const float*)d_in[3];
    const float* b1b  = (const float*)d_in[4];
    const float* b1m  = (const float*)d_in[5];
    const float* b1v  = (const float*)d_in[6];
    const float* w2   = (const float*)d_in[7];
    const float* b2g  = (const float*)d_in[8];
    const float* b2b  = (const float*)d_in[9];
    const float* b2m  = (const float*)d_in[10];
    const float* b2v  = (const float*)d_in[11];
    const float* fc1w = (const float*)d_in[12];
    const float* fc1b = (const float*)d_in[13];
    const float* fc2w = (const float*)d_in[14];
    const float* fc2b = (const float*)d_in[15];

    prep_kernel<<<32, 256>>>(w1, b1g, b1b, b1m, b1v, b2g, b2b, b2m, b2v);
    dim3 gridA(16, 16, 64);
    stageA_kernel<<<gridA, 128>>>(x0, x1);
    stageB_kernel<<<64, 256>>>(w2);
    stageC_kernel<<<32, 256>>>(fc1w, fc1b, fc2w, fc2b, (float*)d_out);
}